// round 8
// baseline (speedup 1.0000x reference)
#include <cuda_runtime.h>

#define N_ROWS  131072
#define DIM     64
#define K_CODES 1024
#define CHUNK   256
#define THREADS 128
#define BLOCKS  (N_ROWS / THREADS)   // 1024
#define KGROUP  8

typedef unsigned long long u64;

__device__ float g_partials[BLOCKS];

// fma.rn.f32x2: two independent lane-wise fp32 FMAs (single rounding each) —
// each lane reproduces a scalar sequential fp32 fma chain bit-exactly.
__device__ __forceinline__ u64 ffma2(u64 a, u64 b, u64 c) {
    u64 d;
    asm("fma.rn.f32x2 %0, %1, %2, %3;" : "=l"(d) : "l"(a), "l"(b), "l"(c));
    return d;
}
__device__ __forceinline__ u64 pack2(float lo, float hi) {
    u64 v;
    asm("mov.b64 %0, {%1, %2};" : "=l"(v) : "f"(lo), "f"(hi));
    return v;
}
__device__ __forceinline__ void unpack2(u64 v, float& lo, float& hi) {
    asm("mov.b64 {%0, %1}, %2;" : "=f"(lo), "=f"(hi) : "l"(v));
}

// One row per thread. Codebook streamed through shared in transposed chunks
// sm_t[j][k] so a single broadcast LDS.128 yields e_{k..k+3}[j].
// Distance replicates the reference's fp32 rounding chain exactly:
//   t_k  = sequential fma over j=0..63 (single accumulator, ascending j)
//   d_k  = fp32( (r + h_k) - 2*t_k )   [2*t exact => one fmaf == two-step]
// argmin with strict '<' over ascending k == first-occurrence tie-break.
__global__ void __launch_bounds__(THREADS, 2)
vq_main(const float* __restrict__ x, const float* __restrict__ cb,
        float* __restrict__ out)
{
    extern __shared__ float sm[];
    float* sm_t = sm;                // [DIM][CHUNK] transposed code chunk
    float* sm_h = sm + DIM * CHUNK;  // [CHUNK] ||e_k||^2

    const int tid = threadIdx.x;
    const int n = blockIdx.x * THREADS + tid;

    // Input row in registers, each element duplicated into both f32x2 lanes.
    u64 xx[DIM];
    float r = 0.0f;                  // ||x||^2 (order irrelevant: uniform shift)
    {
        const float4* xp = (const float4*)(x + (size_t)n * DIM);
#pragma unroll
        for (int q = 0; q < DIM / 4; q++) {
            float4 v = xp[q];
            r += v.x * v.x + v.y * v.y + v.z * v.z + v.w * v.w;
            xx[4 * q + 0] = pack2(v.x, v.x);
            xx[4 * q + 1] = pack2(v.y, v.y);
            xx[4 * q + 2] = pack2(v.z, v.z);
            xx[4 * q + 3] = pack2(v.w, v.w);
        }
    }

    float best  = 3.0e38f;
    int   bestk = 0;

    for (int c = 0; c < K_CODES; c += CHUNK) {
        // ---- stage chunk transposed + per-code squared norms ----
#pragma unroll
        for (int s = 0; s < CHUNK / THREADS; s++) {
            const int k = tid + s * THREADS;
            const float4* src = (const float4*)(cb + (size_t)(c + k) * DIM);
            float ss = 0.0f;
#pragma unroll
            for (int q = 0; q < DIM / 4; q++) {
                float4 v = src[q];
                sm_t[(4 * q + 0) * CHUNK + k] = v.x;
                sm_t[(4 * q + 1) * CHUNK + k] = v.y;
                sm_t[(4 * q + 2) * CHUNK + k] = v.z;
                sm_t[(4 * q + 3) * CHUNK + k] = v.w;
                ss += v.x * v.x + v.y * v.y + v.z * v.z + v.w * v.w;
            }
            sm_h[k] = ss;
        }
        __syncthreads();

        // ---- 8 codes in flight: 4 independent f32x2 chains ----
        for (int k = 0; k < CHUNK; k += KGROUP) {
            u64 a0 = 0, a1 = 0, a2 = 0, a3 = 0;
            const ulonglong2* eA = (const ulonglong2*)(sm_t + k);      // codes k..k+3
            const ulonglong2* eB = (const ulonglong2*)(sm_t + k + 4);  // codes k+4..k+7
#pragma unroll
            for (int j = 0; j < DIM; j++) {              // strictly ascending j
                ulonglong2 ea = eA[j * (CHUNK / 4)];     // broadcast LDS.128
                ulonglong2 eb = eB[j * (CHUNK / 4)];
                a0 = ffma2(xx[j], ea.x, a0);
                a1 = ffma2(xx[j], ea.y, a1);
                a2 = ffma2(xx[j], eb.x, a2);
                a3 = ffma2(xx[j], eb.y, a3);
            }
            float t[8];
            unpack2(a0, t[0], t[1]);
            unpack2(a1, t[2], t[3]);
            unpack2(a2, t[4], t[5]);
            unpack2(a3, t[6], t[7]);
#pragma unroll
            for (int u = 0; u < 8; u++) {
                float A = r + sm_h[k + u];               // fp32(r + h_k)
                float d = fmaf(-2.0f, t[u], A);          // fp32(A - 2t), 2t exact
                if (d < best) { best = d; bestk = c + k + u; }
            }
        }
        __syncthreads();
    }

    // ---- epilogue: gather winner, write outputs, loss partial ----
    // out[0] = loss; out[1 .. 1+N*D) = quantized_st; out[1+N*D ..) = indices
    float* q_out = out + 1;
    float* i_out = out + 1 + (size_t)N_ROWS * DIM;

    const float4* qs = (const float4*)(cb + (size_t)bestk * DIM);
    float* qd = q_out + (size_t)n * DIM;   // base out+1: 4B-aligned -> scalar stores
    float ls = 0.0f;
#pragma unroll
    for (int q = 0; q < DIM / 4; q++) {
        float4 e = qs[q];
        float f0, f1, f2, f3, dummy;
        unpack2(xx[4 * q + 0], f0, dummy);
        unpack2(xx[4 * q + 1], f1, dummy);
        unpack2(xx[4 * q + 2], f2, dummy);
        unpack2(xx[4 * q + 3], f3, dummy);
        float d0 = e.x - f0, d1 = e.y - f1, d2 = e.z - f2, d3 = e.w - f3;
        ls += d0 * d0 + d1 * d1 + d2 * d2 + d3 * d3;
        qd[4 * q + 0] = e.x;
        qd[4 * q + 1] = e.y;
        qd[4 * q + 2] = e.z;
        qd[4 * q + 3] = e.w;
    }
    i_out[n] = (float)bestk;

    // deterministic block reduction of loss partial
#pragma unroll
    for (int o = 16; o > 0; o >>= 1)
        ls += __shfl_down_sync(0xffffffffu, ls, o);
    if ((tid & 31) == 0) sm_h[tid >> 5] = ls;
    __syncthreads();
    if (tid == 0) {
        float t = 0.0f;
#pragma unroll
        for (int w = 0; w < THREADS / 32; w++) t += sm_h[w];
        g_partials[blockIdx.x] = t;
    }
}

__global__ void vq_loss(float* __restrict__ out)
{
    __shared__ float s[BLOCKS];
    const int t = threadIdx.x;
    s[t] = g_partials[t];
    __syncthreads();
    for (int o = BLOCKS / 2; o > 0; o >>= 1) {
        if (t < o) s[t] += s[t + o];
        __syncthreads();
    }
    if (t == 0)
        out[0] = 1.25f * s[0] / (float)(N_ROWS * DIM);
}

extern "C" void kernel_launch(void* const* d_in, const int* in_sizes, int n_in,
                              void* d_out, int out_size)
{
    const float* x  = (const float*)d_in[0];   // inputs   [N, D] fp32
    const float* cb = (const float*)d_in[1];   // codebook [K, D] fp32
    float* out = (float*)d_out;

    const size_t smem = (size_t)(DIM * CHUNK + CHUNK) * sizeof(float); // 66560 B
    cudaFuncSetAttribute(vq_main, cudaFuncAttributeMaxDynamicSharedMemorySize,
                         (int)smem);

    vq_main<<<BLOCKS, THREADS, smem>>>(x, cb, out);
    vq_loss<<<1, BLOCKS>>>(out);
}

// round 9
// speedup vs baseline: 1.2549x; 1.2549x over previous
#include <cuda_runtime.h>

#define N_ROWS  131072
#define DIM     64
#define K_CODES 1024
#define CHUNK   256
#define THREADS 128
#define ROWS_PT 2
#define BLOCKS  (N_ROWS / (THREADS * ROWS_PT))   // 512

typedef unsigned long long u64;

__device__ float g_partials[BLOCKS];

// fma.rn.f32x2: two independent lane-wise fp32 FMAs (single rounding each) —
// each lane reproduces a scalar sequential fp32 fma chain bit-exactly.
__device__ __forceinline__ u64 ffma2(u64 a, u64 b, u64 c) {
    u64 d;
    asm("fma.rn.f32x2 %0, %1, %2, %3;" : "=l"(d) : "l"(a), "l"(b), "l"(c));
    return d;
}
__device__ __forceinline__ u64 pack2(float lo, float hi) {
    u64 v;
    asm("mov.b64 %0, {%1, %2};" : "=l"(v) : "f"(lo), "f"(hi));
    return v;
}
__device__ __forceinline__ void unpack2(u64 v, float& lo, float& hi) {
    asm("mov.b64 {%0, %1}, %2;" : "=f"(lo), "=f"(hi) : "l"(v));
}

// TWO rows per thread: each LDS.128 of codebook data now feeds 8 FFMA2
// (4 per row) instead of 4 — halves the LDS instruction count per FMA,
// which round-8 showed to be the binding pipe.
// Distance replicates the reference's fp32 rounding chain exactly:
//   t_k = sequential fma over j=0..63 (single accumulator, ascending j)
//   d_k = fp32( fp32(r + h_k) - 2*t_k )   (2*t exact => one fmaf)
// argmin: strict '<' over ascending k == jnp.argmin first-occurrence.
__global__ void __launch_bounds__(THREADS, 2)
vq_main(const float* __restrict__ x, const float* __restrict__ cb,
        float* __restrict__ out)
{
    extern __shared__ float sm[];
    float* sm_t = sm;                // [DIM][CHUNK] transposed code chunk
    float* sm_h = sm + DIM * CHUNK;  // [CHUNK] ||e_k||^2

    const int tid = threadIdx.x;
    const int n0 = blockIdx.x * (THREADS * ROWS_PT) + tid;   // row A
    const int n1 = n0 + THREADS;                             // row B (coalesced)

    // Two input rows in scalar fp32 registers (64 + 64 = 128 regs).
    float x0[DIM], x1[DIM];
    float r0 = 0.0f, r1 = 0.0f;      // ||x||^2 (uniform shift: order-free)
    {
        const float4* p0 = (const float4*)(x + (size_t)n0 * DIM);
        const float4* p1 = (const float4*)(x + (size_t)n1 * DIM);
#pragma unroll
        for (int q = 0; q < DIM / 4; q++) {
            float4 v = p0[q];
            r0 += v.x * v.x + v.y * v.y + v.z * v.z + v.w * v.w;
            x0[4 * q] = v.x; x0[4 * q + 1] = v.y; x0[4 * q + 2] = v.z; x0[4 * q + 3] = v.w;
            float4 w = p1[q];
            r1 += w.x * w.x + w.y * w.y + w.z * w.z + w.w * w.w;
            x1[4 * q] = w.x; x1[4 * q + 1] = w.y; x1[4 * q + 2] = w.z; x1[4 * q + 3] = w.w;
        }
    }

    float best0 = 3.0e38f, best1 = 3.0e38f;
    int   bk0 = 0, bk1 = 0;

    for (int c = 0; c < K_CODES; c += CHUNK) {
        // ---- stage chunk transposed (sm_t[j][k]) + per-code squared norms ----
#pragma unroll
        for (int s = 0; s < CHUNK / THREADS; s++) {
            const int k = tid + s * THREADS;
            const float4* src = (const float4*)(cb + (size_t)(c + k) * DIM);
            float ss = 0.0f;
#pragma unroll
            for (int q = 0; q < DIM / 4; q++) {
                float4 v = src[q];
                sm_t[(4 * q + 0) * CHUNK + k] = v.x;
                sm_t[(4 * q + 1) * CHUNK + k] = v.y;
                sm_t[(4 * q + 2) * CHUNK + k] = v.z;
                sm_t[(4 * q + 3) * CHUNK + k] = v.w;
                ss += v.x * v.x + v.y * v.y + v.z * v.z + v.w * v.w;
            }
            sm_h[k] = ss;
        }
        __syncthreads();

        // ---- 8 codes x 2 rows in flight: 8 independent f32x2 chains ----
        for (int k = 0; k < CHUNK; k += 8) {
            u64 a0 = 0, a1 = 0, a2 = 0, a3 = 0;   // row A, codes k..k+7
            u64 b0 = 0, b1 = 0, b2 = 0, b3 = 0;   // row B, codes k..k+7
            const ulonglong2* eA = (const ulonglong2*)(sm_t + k);      // k..k+3
            const ulonglong2* eB = (const ulonglong2*)(sm_t + k + 4);  // k+4..k+7
#pragma unroll
            for (int j = 0; j < DIM; j++) {          // strictly ascending j
                ulonglong2 ea = eA[j * (CHUNK / 4)]; // broadcast LDS.128
                ulonglong2 eb = eB[j * (CHUNK / 4)];
                u64 p0 = pack2(x0[j], x0[j]);        // ALU movs (idle pipe)
                u64 p1 = pack2(x1[j], x1[j]);
                a0 = ffma2(p0, ea.x, a0);
                a1 = ffma2(p0, ea.y, a1);
                a2 = ffma2(p0, eb.x, a2);
                a3 = ffma2(p0, eb.y, a3);
                b0 = ffma2(p1, ea.x, b0);
                b1 = ffma2(p1, ea.y, b1);
                b2 = ffma2(p1, eb.x, b2);
                b3 = ffma2(p1, eb.y, b3);
            }
            float t0[8], t1[8];
            unpack2(a0, t0[0], t0[1]); unpack2(a1, t0[2], t0[3]);
            unpack2(a2, t0[4], t0[5]); unpack2(a3, t0[6], t0[7]);
            unpack2(b0, t1[0], t1[1]); unpack2(b1, t1[2], t1[3]);
            unpack2(b2, t1[4], t1[5]); unpack2(b3, t1[6], t1[7]);
#pragma unroll
            for (int u = 0; u < 8; u++) {
                float h = sm_h[k + u];
                float d0 = fmaf(-2.0f, t0[u], r0 + h);   // fp32((r+h) - 2t)
                float d1 = fmaf(-2.0f, t1[u], r1 + h);
                if (d0 < best0) { best0 = d0; bk0 = c + k + u; }
                if (d1 < best1) { best1 = d1; bk1 = c + k + u; }
            }
        }
        __syncthreads();
    }

    // ---- epilogue: gather winners, write quantized_st + indices, loss ----
    // out[0] = loss; out[1 .. 1+N*D) = quantized_st; out[1+N*D ..) = indices
    float* q_out = out + 1;
    float* i_out = out + 1 + (size_t)N_ROWS * DIM;

    float ls = 0.0f;
    const float4* qs0 = (const float4*)(cb + (size_t)bk0 * DIM);
    const float4* qs1 = (const float4*)(cb + (size_t)bk1 * DIM);
    float* qd0 = q_out + (size_t)n0 * DIM;  // base out+1: 4B-aligned -> scalar stores
    float* qd1 = q_out + (size_t)n1 * DIM;
#pragma unroll
    for (int q = 0; q < DIM / 4; q++) {
        float4 e = qs0[q];
        float f0 = x0[4 * q], f1 = x0[4 * q + 1], f2 = x0[4 * q + 2], f3 = x0[4 * q + 3];
        float d0 = e.x - f0, d1 = e.y - f1, d2 = e.z - f2, d3 = e.w - f3;
        ls += d0 * d0 + d1 * d1 + d2 * d2 + d3 * d3;
        // match reference: quantized_st = x + (q - x), both ops fp32-rounded
        qd0[4 * q + 0] = f0 + d0;
        qd0[4 * q + 1] = f1 + d1;
        qd0[4 * q + 2] = f2 + d2;
        qd0[4 * q + 3] = f3 + d3;
        float4 g = qs1[q];
        float h0 = x1[4 * q], h1 = x1[4 * q + 1], h2 = x1[4 * q + 2], h3 = x1[4 * q + 3];
        float c0 = g.x - h0, c1 = g.y - h1, c2 = g.z - h2, c3 = g.w - h3;
        ls += c0 * c0 + c1 * c1 + c2 * c2 + c3 * c3;
        qd1[4 * q + 0] = h0 + c0;
        qd1[4 * q + 1] = h1 + c1;
        qd1[4 * q + 2] = h2 + c2;
        qd1[4 * q + 3] = h3 + c3;
    }
    i_out[n0] = (float)bk0;
    i_out[n1] = (float)bk1;

    // deterministic block reduction of loss partial
#pragma unroll
    for (int o = 16; o > 0; o >>= 1)
        ls += __shfl_down_sync(0xffffffffu, ls, o);
    if ((tid & 31) == 0) sm_h[tid >> 5] = ls;
    __syncthreads();
    if (tid == 0) {
        float t = 0.0f;
#pragma unroll
        for (int w = 0; w < THREADS / 32; w++) t += sm_h[w];
        g_partials[blockIdx.x] = t;
    }
}

__global__ void vq_loss(float* __restrict__ out)
{
    __shared__ float s[BLOCKS];
    const int t = threadIdx.x;
    s[t] = g_partials[t];
    __syncthreads();
    for (int o = BLOCKS / 2; o > 0; o >>= 1) {
        if (t < o) s[t] += s[t + o];
        __syncthreads();
    }
    if (t == 0)
        out[0] = 1.25f * s[0] / (float)(N_ROWS * DIM);
}

extern "C" void kernel_launch(void* const* d_in, const int* in_sizes, int n_in,
                              void* d_out, int out_size)
{
    const float* x  = (const float*)d_in[0];   // inputs   [N, D] fp32
    const float* cb = (const float*)d_in[1];   // codebook [K, D] fp32
    float* out = (float*)d_out;

    const size_t smem = (size_t)(DIM * CHUNK + CHUNK) * sizeof(float); // 66560 B
    cudaFuncSetAttribute(vq_main, cudaFuncAttributeMaxDynamicSharedMemorySize,
                         (int)smem);

    vq_main<<<BLOCKS, THREADS, smem>>>(x, cb, out);
    vq_loss<<<1, BLOCKS>>>(out);
}